// round 6
// baseline (speedup 1.0000x reference)
#include <cuda_runtime.h>
#include <cstdint>
#include <math.h>

#define D_MODEL 1024
#define NH      16
#define DH      64
#define B_      2
#define S_      2048
#define M_TOK   (B_ * S_)
#define ATT_SCALE 0.125f

// ---------------- scratch (allocation-free) ----------------
__device__ float g_Q[M_TOK * D_MODEL];
__device__ float g_K[M_TOK * D_MODEL];
__device__ float g_V[M_TOK * D_MODEL];
__device__ float g_A[M_TOK * D_MODEL];

// ---------------- helpers (portable PTX only: no tcgen05) ----------------
__device__ __forceinline__ uint32_t f2tf32(float f) {
    uint32_t u;
    asm("cvt.rna.tf32.f32 %0, %1;" : "=r"(u) : "f"(f));
    return u;
}

__device__ __forceinline__ void mma_tf32(float* c, const uint32_t* a, const uint32_t* b) {
    asm volatile(
        "mma.sync.aligned.m16n8k8.row.col.f32.tf32.tf32.f32 "
        "{%0,%1,%2,%3}, {%4,%5,%6,%7}, {%8,%9}, {%0,%1,%2,%3};"
        : "+f"(c[0]), "+f"(c[1]), "+f"(c[2]), "+f"(c[3])
        : "r"(a[0]), "r"(a[1]), "r"(a[2]), "r"(a[3]), "r"(b[0]), "r"(b[1]));
}

// ============================================================================
// tf32 mma.sync NT-GEMM (unchanged — at mma.sync tensor floor)
// ============================================================================
template <bool HEAD_LAYOUT>
__global__ __launch_bounds__(256) void gemm_mma_kernel(
    const float* __restrict__ A,
    const float* __restrict__ W,
    float* __restrict__ C)
{
    __shared__ float As[128][36];
    __shared__ float Bs[128][36];

    const int tid  = threadIdx.x;
    const int wid  = tid >> 5;
    const int lane = tid & 31;
    const int m0   = blockIdx.y * 128;
    const int n0   = blockIdx.x * 128;
    const int wm   = (wid & 3) * 32;
    const int wn   = (wid >> 2) * 64;

    const int lrow = tid >> 3;
    const int lc4  = (tid & 7) * 4;

    const float* aptr = A + (size_t)(m0 + lrow) * D_MODEL + lc4;
    const float* wptr = W + (size_t)(n0 + lrow) * D_MODEL + lc4;

    float4 ar[4], br[4];

    float acc[2][8][4];
#pragma unroll
    for (int mt = 0; mt < 2; mt++)
#pragma unroll
        for (int nt = 0; nt < 8; nt++)
#pragma unroll
            for (int e = 0; e < 4; e++) acc[mt][nt][e] = 0.f;

#pragma unroll
    for (int t = 0; t < 4; t++) {
        ar[t] = *(const float4*)(aptr + (size_t)t * 32 * D_MODEL);
        br[t] = *(const float4*)(wptr + (size_t)t * 32 * D_MODEL);
    }

    for (int i = 0; i < D_MODEL / 32; i++) {
        __syncthreads();
#pragma unroll
        for (int t = 0; t < 4; t++) {
            const int row = lrow + t * 32;
            uint4 ua = make_uint4(f2tf32(ar[t].x), f2tf32(ar[t].y), f2tf32(ar[t].z), f2tf32(ar[t].w));
            uint4 ub = make_uint4(f2tf32(br[t].x), f2tf32(br[t].y), f2tf32(br[t].z), f2tf32(br[t].w));
            *(uint4*)&As[row][lc4] = ua;
            *(uint4*)&Bs[row][lc4] = ub;
        }
        __syncthreads();

        if (i < D_MODEL / 32 - 1) {
            const int k0 = (i + 1) * 32;
#pragma unroll
            for (int t = 0; t < 4; t++) {
                ar[t] = *(const float4*)(aptr + (size_t)t * 32 * D_MODEL + k0);
                br[t] = *(const float4*)(wptr + (size_t)t * 32 * D_MODEL + k0);
            }
        }

#pragma unroll
        for (int ks = 0; ks < 4; ks++) {
            const int kb = ks * 8;
            const int fc = kb + (lane & 3);
            uint32_t a[2][4], b[8][2];
            const int fr = wm + (lane >> 2);
#pragma unroll
            for (int mt = 0; mt < 2; mt++) {
                const int r = fr + mt * 16;
                a[mt][0] = *(const uint32_t*)&As[r][fc];
                a[mt][1] = *(const uint32_t*)&As[r + 8][fc];
                a[mt][2] = *(const uint32_t*)&As[r][fc + 4];
                a[mt][3] = *(const uint32_t*)&As[r + 8][fc + 4];
            }
            const int bn = wn + (lane >> 2);
#pragma unroll
            for (int nt = 0; nt < 8; nt++) {
                b[nt][0] = *(const uint32_t*)&Bs[bn + nt * 8][fc];
                b[nt][1] = *(const uint32_t*)&Bs[bn + nt * 8][fc + 4];
            }
#pragma unroll
            for (int mt = 0; mt < 2; mt++)
#pragma unroll
                for (int nt = 0; nt < 8; nt++)
                    mma_tf32(acc[mt][nt], a[mt], b[nt]);
        }
    }

    const int row  = lane >> 2;
    const int col2 = (lane & 3) * 2;
#pragma unroll
    for (int mt = 0; mt < 2; mt++) {
        const int m = m0 + wm + mt * 16 + row;
#pragma unroll
        for (int nt = 0; nt < 8; nt++) {
            const int n = n0 + wn + nt * 8 + col2;
            if (HEAD_LAYOUT) {
                const int b = m >> 11, s = m & 2047, h = n >> 6, d = n & 63;
                float* dst = C + (((size_t)(b * NH + h) * S_) + s) * DH + d;
                *(float2*)dst = make_float2(acc[mt][nt][0], acc[mt][nt][1]);
                float* dst2 = C + (((size_t)(b * NH + h) * S_) + s + 8) * DH + d;
                *(float2*)dst2 = make_float2(acc[mt][nt][2], acc[mt][nt][3]);
            } else {
                float* dst = C + (size_t)m * D_MODEL + n;
                *(float2*)dst = make_float2(acc[mt][nt][0], acc[mt][nt][1]);
                *(float2*)(dst + 8 * D_MODEL) = make_float2(acc[mt][nt][2], acc[mt][nt][3]);
            }
        }
    }
}

// ============================================================================
// Tensor-core causal flash attention v2.
//  - K stored as paired uint2 in a pos/slot-permuted layout: conflict-free
//    LDS.64 fragment loads AND conflict-free STS.64 staging stores.
//  - V^T stored as paired uint2 (stride 40 words): conflict-free both sides.
//  - P (softmax probs) passed from S C-frags to PV A-frags via intra-quad
//    shfl — no Ps shared-memory round trip.
// K layout: uint2 for (key, ks, tig) = (K[key][8ks+tig], K[key][8ks+tig+4])
//   at word offset key*64 + ((ks+key)&7)*8 + ((tig+(key>>2)+(ks>>2)+2*key)&3)*2
// ============================================================================
__global__ __launch_bounds__(256, 2) void attn_mma_kernel(
    const float* __restrict__ Q,
    const float* __restrict__ K,
    const float* __restrict__ V,
    float* __restrict__ O)
{
    __shared__ uint32_t Ks2[32 * 64];      // 8 KB, paired permuted layout
    __shared__ uint32_t Vt2[64 * 40];      // 10 KB, [dim][key-pairs] stride 40

    const int tid  = threadIdx.x;
    const int wid  = tid >> 5;
    const int lane = tid & 31;
    const int gid  = lane >> 2;            // 0..7
    const int tig  = lane & 3;             // 0..3
    const int bh   = blockIdx.y;
    const int q0   = blockIdx.x * 128;
    const int qr0  = q0 + wid * 16;

    // ---- load Q fragments (once), pre-scaled ----
    const float* Qb = Q + ((size_t)bh * S_ + qr0) * DH;
    uint32_t qa[8][4];
#pragma unroll
    for (int ks = 0; ks < 8; ks++) {
        const int col = ks * 8 + tig;
        qa[ks][0] = f2tf32(Qb[(size_t)gid * DH + col] * ATT_SCALE);
        qa[ks][1] = f2tf32(Qb[(size_t)(gid + 8) * DH + col] * ATT_SCALE);
        qa[ks][2] = f2tf32(Qb[(size_t)gid * DH + col + 4] * ATT_SCALE);
        qa[ks][3] = f2tf32(Qb[(size_t)(gid + 8) * DH + col + 4] * ATT_SCALE);
    }

    float o[8][4];
#pragma unroll
    for (int dt = 0; dt < 8; dt++)
#pragma unroll
        for (int e = 0; e < 4; e++) o[dt][e] = 0.f;
    float mr0 = -1e30f, mr1 = -1e30f;
    float lr0 = 0.f, lr1 = 0.f;

    const int ntiles = blockIdx.x * 4 + 4;

    // staging identities (per-thread constants)
    const int skey = tid >> 3;             // K stage: key 0..31
    const int sks  = tid & 7;              // K stage: k-block 0..7
    const int spos = ((sks + skey) & 7) * 8;
    const int srot = ((skey >> 2) + (sks >> 2) + 2 * skey);
    const int vkey = lane;                 // V stage: key 0..31
    const int vd0  = wid * 8;              // V stage: dim base
    const int vwrd = ((vkey >> 3) << 3) + 2 * (vkey & 3) + ((vkey >> 2) & 1);

    for (int t = 0; t < ntiles; t++) {
        const int krow0 = t * 32;
        __syncthreads();

        // ---- stage K tile (paired permuted layout; coalesced gmem) ----
        {
            const float* kp = K + ((size_t)bh * S_ + krow0 + skey) * DH + sks * 8;
            float4 v0 = *(const float4*)kp;
            float4 v1 = *(const float4*)(kp + 4);
            float d[8] = {v0.x, v0.y, v0.z, v0.w, v1.x, v1.y, v1.z, v1.w};
            uint32_t* row = Ks2 + skey * 64 + spos;
#pragma unroll
            for (int tg = 0; tg < 4; tg++) {
                const int slot = (tg + srot) & 3;
                uint2 u = make_uint2(f2tf32(d[tg]), f2tf32(d[tg + 4]));
                *(uint2*)(row + slot * 2) = u;
            }
        }
        // ---- stage V tile transposed, paired ----
        {
            const float* vp = V + ((size_t)bh * S_ + krow0 + vkey) * DH + vd0;
            float4 v0 = *(const float4*)vp;
            float4 v1 = *(const float4*)(vp + 4);
            float d[8] = {v0.x, v0.y, v0.z, v0.w, v1.x, v1.y, v1.z, v1.w};
#pragma unroll
            for (int i = 0; i < 8; i++)
                Vt2[(vd0 + i) * 40 + vwrd] = f2tf32(d[i]);
        }
        __syncthreads();

        if (krow0 > qr0 + 15) continue;   // warp-uniform causal skip

        // ---- S = Q K^T  (16 x 32 per warp) ----
        float sc[4][4];
#pragma unroll
        for (int nt = 0; nt < 4; nt++)
#pragma unroll
            for (int e = 0; e < 4; e++) sc[nt][e] = 0.f;

        const int g2 = gid >> 2;
#pragma unroll
        for (int ks = 0; ks < 8; ks++) {
            const int pos = ((ks + gid) & 7) * 8;
#pragma unroll
            for (int nt = 0; nt < 4; nt++) {
                const int slot = (tig + 2 * nt + g2 + (ks >> 2) + 2 * gid) & 3;
                uint2 bv = *(const uint2*)(Ks2 + (nt * 8 + gid) * 64 + pos + slot * 2);
                uint32_t b[2] = {bv.x, bv.y};
                mma_tf32(sc[nt], qa[ks], b);
            }
        }

        // ---- causal mask (diagonal tiles only) ----
        const int row0 = qr0 + gid;
        const int row1 = qr0 + 8 + gid;
        if (krow0 + 31 > qr0) {
#pragma unroll
            for (int nt = 0; nt < 4; nt++) {
                const int kc = krow0 + nt * 8 + 2 * tig;
                if (kc > row0)     sc[nt][0] = -1e30f;
                if (kc + 1 > row0) sc[nt][1] = -1e30f;
                if (kc > row1)     sc[nt][2] = -1e30f;
                if (kc + 1 > row1) sc[nt][3] = -1e30f;
            }
        }

        // ---- online softmax on fragments (p overwrites sc) ----
        float tmax0 = -1e30f, tmax1 = -1e30f;
#pragma unroll
        for (int nt = 0; nt < 4; nt++) {
            tmax0 = fmaxf(tmax0, fmaxf(sc[nt][0], sc[nt][1]));
            tmax1 = fmaxf(tmax1, fmaxf(sc[nt][2], sc[nt][3]));
        }
        tmax0 = fmaxf(tmax0, __shfl_xor_sync(0xffffffffu, tmax0, 1));
        tmax0 = fmaxf(tmax0, __shfl_xor_sync(0xffffffffu, tmax0, 2));
        tmax1 = fmaxf(tmax1, __shfl_xor_sync(0xffffffffu, tmax1, 1));
        tmax1 = fmaxf(tmax1, __shfl_xor_sync(0xffffffffu, tmax1, 2));

        const float mn0 = fmaxf(mr0, tmax0);
        const float mn1 = fmaxf(mr1, tmax1);
        const float cr0 = __expf(mr0 - mn0);
        const float cr1 = __expf(mr1 - mn1);

        float sum0 = 0.f, sum1 = 0.f;
#pragma unroll
        for (int nt = 0; nt < 4; nt++) {
            sc[nt][0] = __expf(sc[nt][0] - mn0);
            sc[nt][1] = __expf(sc[nt][1] - mn0);
            sc[nt][2] = __expf(sc[nt][2] - mn1);
            sc[nt][3] = __expf(sc[nt][3] - mn1);
            sum0 += sc[nt][0] + sc[nt][1];
            sum1 += sc[nt][2] + sc[nt][3];
        }
        sum0 += __shfl_xor_sync(0xffffffffu, sum0, 1);
        sum0 += __shfl_xor_sync(0xffffffffu, sum0, 2);
        sum1 += __shfl_xor_sync(0xffffffffu, sum1, 1);
        sum1 += __shfl_xor_sync(0xffffffffu, sum1, 2);

        lr0 = lr0 * cr0 + sum0;
        lr1 = lr1 * cr1 + sum1;
#pragma unroll
        for (int dt = 0; dt < 8; dt++) {
            o[dt][0] *= cr0; o[dt][1] *= cr0;
            o[dt][2] *= cr1; o[dt][3] *= cr1;
        }
        mr0 = mn0; mr1 = mn1;

        // ---- O += P V : P A-frags built via intra-quad shfl ----
        // S C-frag: thread (gid,tig), sc[kb][{0,1}] = P[row0][kb*8 + 2*tig + {0,1}]
        //           sc[kb][{2,3}] = P[row1][...]
        // PV A-frag needed at thread (gid,tig): a[0]=P[row0][kb*8+tig],
        //   a[1]=P[row1][kb*8+tig], a[2]=P[row0][kb*8+tig+4], a[3]=P[row1][kb*8+tig+4]
        // P[r][kb*8+c] lives on lane (r&7)*4 + (c>>1), element (c&1) (+2 if r>=8).
        const int src0 = (gid << 2) + (tig >> 1);   // column c = tig
        const int src1 = src0 + 2;                  // column c = tig+4
        const bool odd = (tig & 1) != 0;
#pragma unroll
        for (int kb = 0; kb < 4; kb++) {
            float g00 = __shfl_sync(0xffffffffu, sc[kb][0], src0);
            float g01 = __shfl_sync(0xffffffffu, sc[kb][1], src0);
            float g02 = __shfl_sync(0xffffffffu, sc[kb][2], src0);
            float g03 = __shfl_sync(0xffffffffu, sc[kb][3], src0);
            float g10 = __shfl_sync(0xffffffffu, sc[kb][0], src1);
            float g11 = __shfl_sync(0xffffffffu, sc[kb][1], src1);
            float g12 = __shfl_sync(0xffffffffu, sc[kb][2], src1);
            float g13 = __shfl_sync(0xffffffffu, sc[kb][3], src1);
            uint32_t pa[4];
            pa[0] = f2tf32(odd ? g01 : g00);
            pa[1] = f2tf32(odd ? g03 : g02);
            pa[2] = f2tf32(odd ? g11 : g10);
            pa[3] = f2tf32(odd ? g13 : g12);
#pragma unroll
            for (int dt = 0; dt < 8; dt++) {
                uint2 bv = *(const uint2*)(Vt2 + (dt * 8 + gid) * 40 + kb * 8 + 2 * tig);
                uint32_t b[2] = {bv.x, bv.y};
                mma_tf32(o[dt], pa, b);
            }
        }
    }

    // ---- epilogue: write token-layout output ----
    const int b  = bh / NH;
    const int h  = bh % NH;
    const float inv0 = 1.f / lr0;
    const float inv1 = 1.f / lr1;
    const int row0 = qr0 + gid;
    const int row1 = qr0 + 8 + gid;
    float* op0 = O + ((size_t)(b * S_ + row0)) * D_MODEL + h * DH;
    float* op1 = O + ((size_t)(b * S_ + row1)) * D_MODEL + h * DH;
#pragma unroll
    for (int dt = 0; dt < 8; dt++) {
        const int d = dt * 8 + 2 * tig;
        *(float2*)(op0 + d) = make_float2(o[dt][0] * inv0, o[dt][1] * inv0);
        *(float2*)(op1 + d) = make_float2(o[dt][2] * inv1, o[dt][3] * inv1);
    }
}

// ============================================================================
// launch
// ============================================================================
extern "C" void kernel_launch(void* const* d_in, const int* in_sizes, int n_in,
                              void* d_out, int out_size)
{
    const float* x  = (const float*)d_in[0];
    const float* Wq = (const float*)d_in[1];
    const float* Wk = (const float*)d_in[2];
    const float* Wv = (const float*)d_in[3];
    const float* Wo = (const float*)d_in[4];
    float* out = (float*)d_out;

    float *Qp, *Kp, *Vp, *Ap;
    cudaGetSymbolAddress((void**)&Qp, g_Q);
    cudaGetSymbolAddress((void**)&Kp, g_K);
    cudaGetSymbolAddress((void**)&Vp, g_V);
    cudaGetSymbolAddress((void**)&Ap, g_A);

    dim3 ggrid(D_MODEL / 128, M_TOK / 128);   // 8 x 32 = 256 CTAs
    gemm_mma_kernel<true><<<ggrid, 256>>>(x, Wq, Qp);
    gemm_mma_kernel<true><<<ggrid, 256>>>(x, Wk, Kp);
    gemm_mma_kernel<true><<<ggrid, 256>>>(x, Wv, Vp);

    dim3 agrid(S_ / 128, B_ * NH);            // 16 x 32
    attn_mma_kernel<<<agrid, 256>>>(Qp, Kp, Vp, Ap);

    gemm_mma_kernel<false><<<ggrid, 256>>>(Ap, Wo, out);
}

// round 7
// speedup vs baseline: 1.1135x; 1.1135x over previous
#include <cuda_runtime.h>
#include <cstdint>
#include <math.h>

#define D_MODEL 1024
#define NH      16
#define DH      64
#define B_      2
#define S_      2048
#define M_TOK   (B_ * S_)

// ---------------- scratch (allocation-free) ----------------
// g_Q/g_K/g_V hold tf32-rounded bit patterns (stored as float); g_Q pre-scaled by 1/8.
__device__ float g_Q[M_TOK * D_MODEL];
__device__ float g_K[M_TOK * D_MODEL];
__device__ float g_V[M_TOK * D_MODEL];
__device__ float g_A[M_TOK * D_MODEL];

// ---------------- helpers (portable PTX only: no tcgen05) ----------------
__device__ __forceinline__ uint32_t f2tf32(float f) {
    uint32_t u;
    asm("cvt.rna.tf32.f32 %0, %1;" : "=r"(u) : "f"(f));
    return u;
}

__device__ __forceinline__ void mma_tf32(float* c, const uint32_t* a, const uint32_t* b) {
    asm volatile(
        "mma.sync.aligned.m16n8k8.row.col.f32.tf32.tf32.f32 "
        "{%0,%1,%2,%3}, {%4,%5,%6,%7}, {%8,%9}, {%0,%1,%2,%3};"
        : "+f"(c[0]), "+f"(c[1]), "+f"(c[2]), "+f"(c[3])
        : "r"(a[0]), "r"(a[1]), "r"(a[2]), "r"(a[3]), "r"(b[0]), "r"(b[1]));
}

__device__ __forceinline__ uint32_t smem_u32(const void* p) {
    uint32_t a;
    asm("{ .reg .u64 t; cvta.to.shared.u64 t, %1; cvt.u32.u64 %0, t; }" : "=r"(a) : "l"(p));
    return a;
}
__device__ __forceinline__ void cp_async16(uint32_t dst, const void* src) {
    asm volatile("cp.async.cg.shared.global [%0], [%1], 16;" :: "r"(dst), "l"(src));
}
#define CP_COMMIT() asm volatile("cp.async.commit_group;" ::: "memory")
#define CP_WAIT1()  asm volatile("cp.async.wait_group 1;"  ::: "memory")

// ============================================================================
// tf32 mma.sync NT-GEMM: C[m][n] = sum_k A[m][k] * W[n][k]
// MODE 0: row-major float output.
// MODE 1: head-layout [B,H,S,Dh], values tf32-rounded (stored as float bits).
// MODE 2: like 1 but pre-scaled by 0.125 (exact power of 2) before rounding.
// ============================================================================
template <int MODE>
__device__ __forceinline__ float epi_cvt(float x) {
    if (MODE == 0) return x;
    if (MODE == 2) x *= 0.125f;
    return __uint_as_float(f2tf32(x));
}

template <int MODE>
__global__ __launch_bounds__(256) void gemm_mma_kernel(
    const float* __restrict__ A,
    const float* __restrict__ W,
    float* __restrict__ C)
{
    __shared__ float As[128][36];
    __shared__ float Bs[128][36];

    const int tid  = threadIdx.x;
    const int wid  = tid >> 5;
    const int lane = tid & 31;
    const int m0   = blockIdx.y * 128;
    const int n0   = blockIdx.x * 128;
    const int wm   = (wid & 3) * 32;
    const int wn   = (wid >> 2) * 64;

    const int lrow = tid >> 3;
    const int lc4  = (tid & 7) * 4;

    const float* aptr = A + (size_t)(m0 + lrow) * D_MODEL + lc4;
    const float* wptr = W + (size_t)(n0 + lrow) * D_MODEL + lc4;

    float4 ar[4], br[4];

    float acc[2][8][4];
#pragma unroll
    for (int mt = 0; mt < 2; mt++)
#pragma unroll
        for (int nt = 0; nt < 8; nt++)
#pragma unroll
            for (int e = 0; e < 4; e++) acc[mt][nt][e] = 0.f;

#pragma unroll
    for (int t = 0; t < 4; t++) {
        ar[t] = *(const float4*)(aptr + (size_t)t * 32 * D_MODEL);
        br[t] = *(const float4*)(wptr + (size_t)t * 32 * D_MODEL);
    }

    for (int i = 0; i < D_MODEL / 32; i++) {
        __syncthreads();
#pragma unroll
        for (int t = 0; t < 4; t++) {
            const int row = lrow + t * 32;
            uint4 ua = make_uint4(f2tf32(ar[t].x), f2tf32(ar[t].y), f2tf32(ar[t].z), f2tf32(ar[t].w));
            uint4 ub = make_uint4(f2tf32(br[t].x), f2tf32(br[t].y), f2tf32(br[t].z), f2tf32(br[t].w));
            *(uint4*)&As[row][lc4] = ua;
            *(uint4*)&Bs[row][lc4] = ub;
        }
        __syncthreads();

        if (i < D_MODEL / 32 - 1) {
            const int k0 = (i + 1) * 32;
#pragma unroll
            for (int t = 0; t < 4; t++) {
                ar[t] = *(const float4*)(aptr + (size_t)t * 32 * D_MODEL + k0);
                br[t] = *(const float4*)(wptr + (size_t)t * 32 * D_MODEL + k0);
            }
        }

#pragma unroll
        for (int ks = 0; ks < 4; ks++) {
            const int kb = ks * 8;
            const int fc = kb + (lane & 3);
            uint32_t a[2][4], b[8][2];
            const int fr = wm + (lane >> 2);
#pragma unroll
            for (int mt = 0; mt < 2; mt++) {
                const int r = fr + mt * 16;
                a[mt][0] = *(const uint32_t*)&As[r][fc];
                a[mt][1] = *(const uint32_t*)&As[r + 8][fc];
                a[mt][2] = *(const uint32_t*)&As[r][fc + 4];
                a[mt][3] = *(const uint32_t*)&As[r + 8][fc + 4];
            }
            const int bn = wn + (lane >> 2);
#pragma unroll
            for (int nt = 0; nt < 8; nt++) {
                b[nt][0] = *(const uint32_t*)&Bs[bn + nt * 8][fc];
                b[nt][1] = *(const uint32_t*)&Bs[bn + nt * 8][fc + 4];
            }
#pragma unroll
            for (int mt = 0; mt < 2; mt++)
#pragma unroll
                for (int nt = 0; nt < 8; nt++)
                    mma_tf32(acc[mt][nt], a[mt], b[nt]);
        }
    }

    const int row  = lane >> 2;
    const int col2 = (lane & 3) * 2;
#pragma unroll
    for (int mt = 0; mt < 2; mt++) {
        const int m = m0 + wm + mt * 16 + row;
#pragma unroll
        for (int nt = 0; nt < 8; nt++) {
            const int n = n0 + wn + nt * 8 + col2;
            float e0 = epi_cvt<MODE>(acc[mt][nt][0]);
            float e1 = epi_cvt<MODE>(acc[mt][nt][1]);
            float e2 = epi_cvt<MODE>(acc[mt][nt][2]);
            float e3 = epi_cvt<MODE>(acc[mt][nt][3]);
            if (MODE != 0) {
                const int b = m >> 11, s = m & 2047, h = n >> 6, d = n & 63;
                float* dst = C + (((size_t)(b * NH + h) * S_) + s) * DH + d;
                *(float2*)dst = make_float2(e0, e1);
                float* dst2 = C + (((size_t)(b * NH + h) * S_) + s + 8) * DH + d;
                *(float2*)dst2 = make_float2(e2, e3);
            } else {
                float* dst = C + (size_t)m * D_MODEL + n;
                *(float2*)dst = make_float2(e0, e1);
                *(float2*)(dst + 8 * D_MODEL) = make_float2(e2, e3);
            }
        }
    }
}

// ============================================================================
// Tensor-core causal flash attention v3: cp.async double-buffered K/V.
// Inputs Q/K/V already tf32-rounded (Q pre-scaled by 1/8) by GEMM epilogue.
// smem (dynamic, words): per buffer p: K at p*4480 [32][68], V at p*4480+2176
// [32][72] (k-major); Ps at 8960, per-warp [16][36]. Total 13568 words = 54272 B.
// ============================================================================
#define KV_BUF   4480
#define K_STRIDE 68
#define V_STRIDE 72
#define V_OFF    2176
#define PS_OFF   8960
#define ATT_SMEM 54272

__global__ __launch_bounds__(256, 2) void attn_mma_kernel(
    const float* __restrict__ Q,
    const float* __restrict__ K,
    const float* __restrict__ V,
    float* __restrict__ O)
{
    extern __shared__ uint32_t dsm[];
    const uint32_t sbase = smem_u32(dsm);

    const int tid  = threadIdx.x;
    const int wid  = tid >> 5;
    const int lane = tid & 31;
    const int gid  = lane >> 2;            // 0..7
    const int tig  = lane & 3;             // 0..3
    const int bh   = blockIdx.y;
    const int qr0  = blockIdx.x * 128 + wid * 16;

    const int ntiles = blockIdx.x * 4 + 4;

    // cp.async staging identities: 2 K-chunks + 2 V-chunks per thread per tile
    const int crow0 = tid >> 4;            // 0..15
    const int cc16  = (tid & 15) * 4;      // word offset 0..60
    const float* Kg = K + (size_t)bh * S_ * DH;
    const float* Vg = V + (size_t)bh * S_ * DH;

    // ---- issue helper (macro-free inline) ----
    auto issue_tile = [&](int t, int p) {
        const size_t rowbase = (size_t)t * 32;
#pragma unroll
        for (int i = 0; i < 2; i++) {
            const int row = crow0 + i * 16;
            const float* ks = Kg + (rowbase + row) * DH + cc16;
            const float* vs = Vg + (rowbase + row) * DH + cc16;
            cp_async16(sbase + (p * KV_BUF + row * K_STRIDE + cc16) * 4, ks);
            cp_async16(sbase + (p * KV_BUF + V_OFF + row * V_STRIDE + cc16) * 4, vs);
        }
    };

    // ---- load Q fragments (tf32 bits, pre-scaled; no cvt) ----
    const uint32_t* Qb = (const uint32_t*)(Q + ((size_t)bh * S_ + qr0) * DH);
    uint32_t qa[8][4];
#pragma unroll
    for (int ks = 0; ks < 8; ks++) {
        const int col = ks * 8 + tig;
        qa[ks][0] = Qb[(size_t)gid * DH + col];
        qa[ks][1] = Qb[(size_t)(gid + 8) * DH + col];
        qa[ks][2] = Qb[(size_t)gid * DH + col + 4];
        qa[ks][3] = Qb[(size_t)(gid + 8) * DH + col + 4];
    }

    float o[8][4];
#pragma unroll
    for (int dt = 0; dt < 8; dt++)
#pragma unroll
        for (int e = 0; e < 4; e++) o[dt][e] = 0.f;
    float mr0 = -1e30f, mr1 = -1e30f;
    float lr0 = 0.f, lr1 = 0.f;

    // prefetch tiles 0 and 1
    issue_tile(0, 0); CP_COMMIT();
    issue_tile(1, 1); CP_COMMIT();

    uint32_t* Pw = dsm + PS_OFF + wid * 576;   // per-warp [16][36]

    for (int t = 0; t < ntiles; t++) {
        CP_WAIT1();
        __syncthreads();

        const int krow0 = t * 32;
        const int p = t & 1;

        if (krow0 <= qr0 + 15) {
            const uint32_t* Ksm = dsm + p * KV_BUF;
            const uint32_t* Vsm = dsm + p * KV_BUF + V_OFF;

            // ---- S = Q K^T (16 x 32 per warp) ----
            float sc[4][4];
#pragma unroll
            for (int nt = 0; nt < 4; nt++)
#pragma unroll
                for (int e = 0; e < 4; e++) sc[nt][e] = 0.f;
#pragma unroll
            for (int ks = 0; ks < 8; ks++) {
                const int fc = ks * 8 + tig;
#pragma unroll
                for (int nt = 0; nt < 4; nt++) {
                    const uint32_t* krow = Ksm + (nt * 8 + gid) * K_STRIDE;
                    uint32_t b[2] = {krow[fc], krow[fc + 4]};
                    mma_tf32(sc[nt], qa[ks], b);
                }
            }

            // ---- causal mask (diagonal tiles only) ----
            const int row0 = qr0 + gid;
            const int row1 = qr0 + 8 + gid;
            if (krow0 + 31 > qr0) {
#pragma unroll
                for (int nt = 0; nt < 4; nt++) {
                    const int kc = krow0 + nt * 8 + 2 * tig;
                    if (kc > row0)     sc[nt][0] = -1e30f;
                    if (kc + 1 > row0) sc[nt][1] = -1e30f;
                    if (kc > row1)     sc[nt][2] = -1e30f;
                    if (kc + 1 > row1) sc[nt][3] = -1e30f;
                }
            }

            // ---- online softmax ----
            float tmax0 = -1e30f, tmax1 = -1e30f;
#pragma unroll
            for (int nt = 0; nt < 4; nt++) {
                tmax0 = fmaxf(tmax0, fmaxf(sc[nt][0], sc[nt][1]));
                tmax1 = fmaxf(tmax1, fmaxf(sc[nt][2], sc[nt][3]));
            }
            tmax0 = fmaxf(tmax0, __shfl_xor_sync(0xffffffffu, tmax0, 1));
            tmax0 = fmaxf(tmax0, __shfl_xor_sync(0xffffffffu, tmax0, 2));
            tmax1 = fmaxf(tmax1, __shfl_xor_sync(0xffffffffu, tmax1, 1));
            tmax1 = fmaxf(tmax1, __shfl_xor_sync(0xffffffffu, tmax1, 2));

            const float mn0 = fmaxf(mr0, tmax0);
            const float mn1 = fmaxf(mr1, tmax1);
            const float cr0 = __expf(mr0 - mn0);
            const float cr1 = __expf(mr1 - mn1);

            float sum0 = 0.f, sum1 = 0.f;
#pragma unroll
            for (int nt = 0; nt < 4; nt++) {
                float p0 = __expf(sc[nt][0] - mn0);
                float p1 = __expf(sc[nt][1] - mn0);
                float p2 = __expf(sc[nt][2] - mn1);
                float p3 = __expf(sc[nt][3] - mn1);
                sum0 += p0 + p1;
                sum1 += p2 + p3;
                const int col = nt * 8 + 2 * tig;
                *(uint2*)(Pw + gid * 36 + col)       = make_uint2(f2tf32(p0), f2tf32(p1));
                *(uint2*)(Pw + (gid + 8) * 36 + col) = make_uint2(f2tf32(p2), f2tf32(p3));
            }
            sum0 += __shfl_xor_sync(0xffffffffu, sum0, 1);
            sum0 += __shfl_xor_sync(0xffffffffu, sum0, 2);
            sum1 += __shfl_xor_sync(0xffffffffu, sum1, 1);
            sum1 += __shfl_xor_sync(0xffffffffu, sum1, 2);

            lr0 = lr0 * cr0 + sum0;
            lr1 = lr1 * cr1 + sum1;
#pragma unroll
            for (int dt = 0; dt < 8; dt++) {
                o[dt][0] *= cr0; o[dt][1] *= cr0;
                o[dt][2] *= cr1; o[dt][3] *= cr1;
            }
            mr0 = mn0; mr1 = mn1;
            __syncwarp();

            // ---- O += P V  (V k-major in smem) ----
#pragma unroll
            for (int kb = 0; kb < 4; kb++) {
                const int kc = kb * 8 + tig;
                uint32_t pa[4];
                pa[0] = Pw[gid * 36 + kc];
                pa[1] = Pw[(gid + 8) * 36 + kc];
                pa[2] = Pw[gid * 36 + kc + 4];
                pa[3] = Pw[(gid + 8) * 36 + kc + 4];
#pragma unroll
                for (int dt = 0; dt < 8; dt++) {
                    uint32_t b[2];
                    b[0] = Vsm[(kb * 8 + tig) * V_STRIDE + dt * 8 + gid];
                    b[1] = Vsm[(kb * 8 + tig + 4) * V_STRIDE + dt * 8 + gid];
                    mma_tf32(o[dt], pa, b);
                }
            }
            __syncwarp();
        }

        __syncthreads();
        if (t + 2 < ntiles) issue_tile(t + 2, p);
        CP_COMMIT();
    }

    // ---- epilogue: write token-layout output ----
    const int b  = bh / NH;
    const int h  = bh % NH;
    const float inv0 = 1.f / lr0;
    const float inv1 = 1.f / lr1;
    const int row0 = qr0 + gid;
    const int row1 = qr0 + 8 + gid;
    float* op0 = O + ((size_t)(b * S_ + row0)) * D_MODEL + h * DH;
    float* op1 = O + ((size_t)(b * S_ + row1)) * D_MODEL + h * DH;
#pragma unroll
    for (int dt = 0; dt < 8; dt++) {
        const int d = dt * 8 + 2 * tig;
        *(float2*)(op0 + d) = make_float2(o[dt][0] * inv0, o[dt][1] * inv0);
        *(float2*)(op1 + d) = make_float2(o[dt][2] * inv1, o[dt][3] * inv1);
    }
}

// ============================================================================
// launch
// ============================================================================
extern "C" void kernel_launch(void* const* d_in, const int* in_sizes, int n_in,
                              void* d_out, int out_size)
{
    const float* x  = (const float*)d_in[0];
    const float* Wq = (const float*)d_in[1];
    const float* Wk = (const float*)d_in[2];
    const float* Wv = (const float*)d_in[3];
    const float* Wo = (const float*)d_in[4];
    float* out = (float*)d_out;

    float *Qp, *Kp, *Vp, *Ap;
    cudaGetSymbolAddress((void**)&Qp, g_Q);
    cudaGetSymbolAddress((void**)&Kp, g_K);
    cudaGetSymbolAddress((void**)&Vp, g_V);
    cudaGetSymbolAddress((void**)&Ap, g_A);

    cudaFuncSetAttribute(attn_mma_kernel,
                         cudaFuncAttributeMaxDynamicSharedMemorySize, ATT_SMEM);

    dim3 ggrid(D_MODEL / 128, M_TOK / 128);   // 8 x 32 = 256 CTAs
    gemm_mma_kernel<2><<<ggrid, 256>>>(x, Wq, Qp);   // Q: tf32 + prescale
    gemm_mma_kernel<1><<<ggrid, 256>>>(x, Wk, Kp);   // K: tf32
    gemm_mma_kernel<1><<<ggrid, 256>>>(x, Wv, Vp);   // V: tf32

    dim3 agrid(S_ / 128, B_ * NH);            // 16 x 32
    attn_mma_kernel<<<agrid, 256, ATT_SMEM>>>(Qp, Kp, Vp, Ap);

    gemm_mma_kernel<0><<<ggrid, 256>>>(Ap, Wo, out); // O projection, fp32 out
}

// round 8
// speedup vs baseline: 1.8924x; 1.6994x over previous
#include <cuda_runtime.h>
#include <cuda_fp16.h>
#include <cstdint>
#include <math.h>

#define D_MODEL 1024
#define NH      16
#define DH      64
#define B_      2
#define S_      2048
#define M_TOK   (B_ * S_)

// ---------------- scratch (allocation-free) ----------------
// Q/K/V/A intermediates in fp16 (Q pre-scaled by 1/8 exactly).
__device__ __half g_Q[M_TOK * D_MODEL];
__device__ __half g_K[M_TOK * D_MODEL];
__device__ __half g_V[M_TOK * D_MODEL];
__device__ __half g_A[M_TOK * D_MODEL];

// ---------------- helpers (portable PTX: mma.sync / ldmatrix / cp.async) ----
__device__ __forceinline__ uint32_t pack_h2(float a, float b) {
    __half2 h = __floats2half2_rn(a, b);
    return *(uint32_t*)&h;
}

__device__ __forceinline__ void mma_f16(float* c, const uint32_t* a, const uint32_t* b) {
    asm volatile(
        "mma.sync.aligned.m16n8k16.row.col.f32.f16.f16.f32 "
        "{%0,%1,%2,%3}, {%4,%5,%6,%7}, {%8,%9}, {%0,%1,%2,%3};"
        : "+f"(c[0]), "+f"(c[1]), "+f"(c[2]), "+f"(c[3])
        : "r"(a[0]), "r"(a[1]), "r"(a[2]), "r"(a[3]), "r"(b[0]), "r"(b[1]));
}

__device__ __forceinline__ void ldsm_x4(uint32_t* r, uint32_t addr) {
    asm volatile("ldmatrix.sync.aligned.m8n8.x4.shared.b16 {%0,%1,%2,%3}, [%4];"
        : "=r"(r[0]), "=r"(r[1]), "=r"(r[2]), "=r"(r[3]) : "r"(addr));
}
__device__ __forceinline__ void ldsm_x4_t(uint32_t* r, uint32_t addr) {
    asm volatile("ldmatrix.sync.aligned.m8n8.x4.trans.shared.b16 {%0,%1,%2,%3}, [%4];"
        : "=r"(r[0]), "=r"(r[1]), "=r"(r[2]), "=r"(r[3]) : "r"(addr));
}

__device__ __forceinline__ uint32_t smem_u32(const void* p) {
    uint32_t a;
    asm("{ .reg .u64 t; cvta.to.shared.u64 t, %1; cvt.u32.u64 %0, t; }" : "=r"(a) : "l"(p));
    return a;
}
__device__ __forceinline__ void cp_async16(uint32_t dst, const void* src) {
    asm volatile("cp.async.cg.shared.global [%0], [%1], 16;" :: "r"(dst), "l"(src));
}
#define CP_COMMIT() asm volatile("cp.async.commit_group;" ::: "memory")
#define CP_WAIT1()  asm volatile("cp.async.wait_group 1;"  ::: "memory")

// ============================================================================
// fp16 mma.sync NT-GEMM: C[m][n] = sum_k A[m][k] * W[n][k]
// CTA 128x128, 8 warps (4m x 2n), warp 32x64. K-chunk 32, stride 20 words.
// MODE 0: float row-major out. MODE 1: half head-layout. MODE 2: half
// head-layout pre-scaled by 0.125. AHALF: A operand already fp16.
// ============================================================================
#define GSTR 20   // smem row stride in words (40 halves)

template <int MODE, bool AHALF>
__global__ __launch_bounds__(256) void gemm_f16_kernel(
    const void* __restrict__ Av,
    const float* __restrict__ W,
    void* __restrict__ Cv)
{
    __shared__ uint32_t Asm[128 * GSTR];
    __shared__ uint32_t Bsm[128 * GSTR];
    const uint32_t sA = smem_u32(Asm);
    const uint32_t sB = smem_u32(Bsm);

    const int tid  = threadIdx.x;
    const int wid  = tid >> 5;
    const int lane = tid & 31;
    const int m0   = blockIdx.y * 128;
    const int n0   = blockIdx.x * 128;
    const int wm   = (wid & 3) * 32;
    const int wn   = (wid >> 2) * 64;

    const int lrow = tid >> 3;          // 0..31 (+t*32)
    const int lc4  = (tid & 7) * 4;     // half/float offset within 32-k chunk

    // ldmatrix per-lane address offsets (words)
    const int a_off = ((lane & 7) + ((lane >> 3) & 1) * 8) * GSTR + (lane >> 4) * 4;
    const int b_off = ((lane & 7) + (lane >> 4) * 8) * GSTR + ((lane >> 3) & 1) * 4;

    const float*  Af = (const float*)Av;
    const __half* Ah = (const __half*)Av;

    float4 ar[4]; uint2 ah[4]; float4 br[4];

    float acc[2][8][4];
#pragma unroll
    for (int mt = 0; mt < 2; mt++)
#pragma unroll
        for (int nt = 0; nt < 8; nt++)
#pragma unroll
            for (int e = 0; e < 4; e++) acc[mt][nt][e] = 0.f;

    // prefetch chunk 0
#pragma unroll
    for (int t = 0; t < 4; t++) {
        const size_t row = (size_t)(m0 + lrow + t * 32);
        if (AHALF) ah[t] = *(const uint2*)(Ah + row * D_MODEL + lc4);
        else       ar[t] = *(const float4*)(Af + row * D_MODEL + lc4);
        br[t] = *(const float4*)(W + (size_t)(n0 + lrow + t * 32) * D_MODEL + lc4);
    }

    for (int i = 0; i < D_MODEL / 32; i++) {
        __syncthreads();
#pragma unroll
        for (int t = 0; t < 4; t++) {
            const int row = lrow + t * 32;
            uint2 ua;
            if (AHALF) ua = ah[t];
            else       ua = make_uint2(pack_h2(ar[t].x, ar[t].y), pack_h2(ar[t].z, ar[t].w));
            uint2 ub = make_uint2(pack_h2(br[t].x, br[t].y), pack_h2(br[t].z, br[t].w));
            *(uint2*)&Asm[row * GSTR + (tid & 7) * 2] = ua;
            *(uint2*)&Bsm[row * GSTR + (tid & 7) * 2] = ub;
        }
        __syncthreads();

        if (i < D_MODEL / 32 - 1) {
            const int k0 = (i + 1) * 32;
#pragma unroll
            for (int t = 0; t < 4; t++) {
                const size_t row = (size_t)(m0 + lrow + t * 32);
                if (AHALF) ah[t] = *(const uint2*)(Ah + row * D_MODEL + k0 + lc4);
                else       ar[t] = *(const float4*)(Af + row * D_MODEL + k0 + lc4);
                br[t] = *(const float4*)(W + (size_t)(n0 + lrow + t * 32) * D_MODEL + k0 + lc4);
            }
        }

#pragma unroll
        for (int ks = 0; ks < 2; ks++) {     // two k16 steps per 32-k chunk
            uint32_t a[2][4], bfr[4][4];
            ldsm_x4(a[0], sA + 4 * ((wm)      * GSTR + ks * 8 + a_off));
            ldsm_x4(a[1], sA + 4 * ((wm + 16) * GSTR + ks * 8 + a_off));
#pragma unroll
            for (int np = 0; np < 4; np++)
                ldsm_x4(bfr[np], sB + 4 * ((wn + np * 16) * GSTR + ks * 8 + b_off));
#pragma unroll
            for (int mt = 0; mt < 2; mt++)
#pragma unroll
                for (int nt = 0; nt < 8; nt++)
                    mma_f16(acc[mt][nt], a[mt], &bfr[nt >> 1][(nt & 1) * 2]);
        }
    }

    const int row  = lane >> 2;
    const int col2 = (lane & 3) * 2;
#pragma unroll
    for (int mt = 0; mt < 2; mt++) {
        const int m = m0 + wm + mt * 16 + row;
#pragma unroll
        for (int nt = 0; nt < 8; nt++) {
            const int n = n0 + wn + nt * 8 + col2;
            if (MODE != 0) {
                const float sc = (MODE == 2) ? 0.125f : 1.0f;
                uint32_t h01 = pack_h2(acc[mt][nt][0] * sc, acc[mt][nt][1] * sc);
                uint32_t h23 = pack_h2(acc[mt][nt][2] * sc, acc[mt][nt][3] * sc);
                const int b = m >> 11, s = m & 2047, h = n >> 6, d = n & 63;
                __half* Ch = (__half*)Cv;
                __half* dst = Ch + (((size_t)(b * NH + h) * S_) + s) * DH + d;
                *(uint32_t*)dst = h01;
                *(uint32_t*)(dst + (size_t)8 * DH) = h23;
            } else {
                float* Cf = (float*)Cv;
                float* dst = Cf + (size_t)m * D_MODEL + n;
                *(float2*)dst = make_float2(acc[mt][nt][0], acc[mt][nt][1]);
                *(float2*)(dst + 8 * D_MODEL) = make_float2(acc[mt][nt][2], acc[mt][nt][3]);
            }
        }
    }
}

// ============================================================================
// fp16 tensor-core causal flash attention: cp.async double-buffered K/V,
// ldmatrix fragments (K/P non-trans, V trans), online softmax on C-frags.
// smem (words): K tile [32][36], V tile [32][36] per buffer (x2); Ps per warp
// [16][20]. K/V rows: 64 halves data + 8 pad. Total 7168 words = 28 KB.
// ============================================================================
#define KVW   2304          // words per buffer (K 1152 + V 1152)
#define KVS   36            // K/V row stride (words)
#define VOFFW 1152
#define PSOFF 4608
#define PSTR  20            // Ps row stride (words)

__global__ __launch_bounds__(256, 2) void attn_f16_kernel(
    const __half* __restrict__ Q,
    const __half* __restrict__ K,
    const __half* __restrict__ V,
    __half* __restrict__ O)
{
    __shared__ uint32_t sm[7168];
    const uint32_t sbase = smem_u32(sm);

    const int tid  = threadIdx.x;
    const int wid  = tid >> 5;
    const int lane = tid & 31;
    const int gid  = lane >> 2;
    const int tig  = lane & 3;
    const int bh   = blockIdx.y;
    const int qr0  = blockIdx.x * 128 + wid * 16;
    const int ntiles = blockIdx.x * 4 + 4;

    // cp.async staging: 1 chunk of K + 1 of V per thread per tile
    const int crow = tid >> 3;           // 0..31
    const int cch  = tid & 7;            // 16B chunk in row
    const __half* Kg = K + (size_t)bh * S_ * DH;
    const __half* Vg = V + (size_t)bh * S_ * DH;

    auto issue_tile = [&](int t, int p) {
        const size_t row = (size_t)t * 32 + crow;
        cp_async16(sbase + 4 * (p * KVW + crow * KVS + cch * 4),        Kg + row * DH + cch * 8);
        cp_async16(sbase + 4 * (p * KVW + VOFFW + crow * KVS + cch * 4), Vg + row * DH + cch * 8);
    };

    // ldmatrix per-lane offsets (words)
    const int kb_off = ((lane & 7) + (lane >> 4) * 8) * KVS + ((lane >> 3) & 1) * 4;
    const int v_off  = (lane & 15) * KVS + (lane >> 4) * 4;
    const int p_off  = ((lane & 7) + ((lane >> 3) & 1) * 8) * PSTR + (lane >> 4) * 4;

    // ---- Q fragments (fp16, pre-scaled; 4 k16 steps) ----
    const uint32_t* Qw = (const uint32_t*)(Q + ((size_t)bh * S_ + qr0) * DH);
    uint32_t qa[4][4];
#pragma unroll
    for (int ks = 0; ks < 4; ks++) {
        qa[ks][0] = Qw[(size_t)gid * 32 + ks * 8 + tig];
        qa[ks][1] = Qw[(size_t)(gid + 8) * 32 + ks * 8 + tig];
        qa[ks][2] = Qw[(size_t)gid * 32 + ks * 8 + tig + 4];
        qa[ks][3] = Qw[(size_t)(gid + 8) * 32 + ks * 8 + tig + 4];
    }

    float o[8][4];
#pragma unroll
    for (int dt = 0; dt < 8; dt++)
#pragma unroll
        for (int e = 0; e < 4; e++) o[dt][e] = 0.f;
    float mr0 = -1e30f, mr1 = -1e30f;
    float lr0 = 0.f, lr1 = 0.f;

    issue_tile(0, 0); CP_COMMIT();
    issue_tile(1, 1); CP_COMMIT();

    uint32_t* Pw = sm + PSOFF + wid * 16 * PSTR;
    const uint32_t pwbase = sbase + 4 * (PSOFF + wid * 16 * PSTR);

    for (int t = 0; t < ntiles; t++) {
        CP_WAIT1();
        __syncthreads();

        const int krow0 = t * 32;
        const int p = t & 1;

        if (krow0 <= qr0 + 15) {
            const uint32_t kbase = sbase + 4 * (p * KVW);
            const uint32_t vbase = sbase + 4 * (p * KVW + VOFFW);

            // ---- S = Q K^T ----
            float sc[4][4];
#pragma unroll
            for (int nt = 0; nt < 4; nt++)
#pragma unroll
                for (int e = 0; e < 4; e++) sc[nt][e] = 0.f;
#pragma unroll
            for (int ks = 0; ks < 4; ks++) {
                uint32_t bk[2][4];
                ldsm_x4(bk[0], kbase + 4 * (ks * 8 + kb_off));
                ldsm_x4(bk[1], kbase + 4 * (16 * KVS + ks * 8 + kb_off));
#pragma unroll
                for (int nt = 0; nt < 4; nt++)
                    mma_f16(sc[nt], qa[ks], &bk[nt >> 1][(nt & 1) * 2]);
            }

            // ---- causal mask (diagonal tiles only) ----
            const int row0 = qr0 + gid;
            const int row1 = qr0 + 8 + gid;
            if (krow0 + 31 > qr0) {
#pragma unroll
                for (int nt = 0; nt < 4; nt++) {
                    const int kc = krow0 + nt * 8 + 2 * tig;
                    if (kc > row0)     sc[nt][0] = -1e30f;
                    if (kc + 1 > row0) sc[nt][1] = -1e30f;
                    if (kc > row1)     sc[nt][2] = -1e30f;
                    if (kc + 1 > row1) sc[nt][3] = -1e30f;
                }
            }

            // ---- online softmax ----
            float tmax0 = -1e30f, tmax1 = -1e30f;
#pragma unroll
            for (int nt = 0; nt < 4; nt++) {
                tmax0 = fmaxf(tmax0, fmaxf(sc[nt][0], sc[nt][1]));
                tmax1 = fmaxf(tmax1, fmaxf(sc[nt][2], sc[nt][3]));
            }
            tmax0 = fmaxf(tmax0, __shfl_xor_sync(0xffffffffu, tmax0, 1));
            tmax0 = fmaxf(tmax0, __shfl_xor_sync(0xffffffffu, tmax0, 2));
            tmax1 = fmaxf(tmax1, __shfl_xor_sync(0xffffffffu, tmax1, 1));
            tmax1 = fmaxf(tmax1, __shfl_xor_sync(0xffffffffu, tmax1, 2));

            const float mn0 = fmaxf(mr0, tmax0);
            const float mn1 = fmaxf(mr1, tmax1);
            const float cr0 = __expf(mr0 - mn0);
            const float cr1 = __expf(mr1 - mn1);

            float sum0 = 0.f, sum1 = 0.f;
#pragma unroll
            for (int nt = 0; nt < 4; nt++) {
                float p0 = __expf(sc[nt][0] - mn0);
                float p1 = __expf(sc[nt][1] - mn0);
                float p2 = __expf(sc[nt][2] - mn1);
                float p3 = __expf(sc[nt][3] - mn1);
                sum0 += p0 + p1;
                sum1 += p2 + p3;
                Pw[gid * PSTR + nt * 4 + tig]       = pack_h2(p0, p1);
                Pw[(gid + 8) * PSTR + nt * 4 + tig] = pack_h2(p2, p3);
            }
            sum0 += __shfl_xor_sync(0xffffffffu, sum0, 1);
            sum0 += __shfl_xor_sync(0xffffffffu, sum0, 2);
            sum1 += __shfl_xor_sync(0xffffffffu, sum1, 1);
            sum1 += __shfl_xor_sync(0xffffffffu, sum1, 2);

            lr0 = lr0 * cr0 + sum0;
            lr1 = lr1 * cr1 + sum1;
#pragma unroll
            for (int dt = 0; dt < 8; dt++) {
                o[dt][0] *= cr0; o[dt][1] *= cr0;
                o[dt][2] *= cr1; o[dt][3] *= cr1;
            }
            mr0 = mn0; mr1 = mn1;
            __syncwarp();

            // ---- O += P V (V frags via ldmatrix.trans) ----
#pragma unroll
            for (int kb = 0; kb < 2; kb++) {
                uint32_t pa[4];
                ldsm_x4(pa, pwbase + 4 * (kb * 8 + p_off));
#pragma unroll
                for (int dp = 0; dp < 4; dp++) {
                    uint32_t bv[4];
                    ldsm_x4_t(bv, vbase + 4 * (kb * 16 * KVS + dp * 8 + v_off));
                    mma_f16(o[2 * dp],     pa, &bv[0]);
                    mma_f16(o[2 * dp + 1], pa, &bv[2]);
                }
            }
            __syncwarp();
        }

        __syncthreads();
        if (t + 2 < ntiles) issue_tile(t + 2, p);
        CP_COMMIT();
    }

    // ---- epilogue: fp16 token-layout output ----
    const int b  = bh / NH;
    const int h  = bh % NH;
    const float inv0 = 1.f / lr0;
    const float inv1 = 1.f / lr1;
    const int row0 = qr0 + gid;
    const int row1 = qr0 + 8 + gid;
    __half* op0 = O + ((size_t)(b * S_ + row0)) * D_MODEL + h * DH;
    __half* op1 = O + ((size_t)(b * S_ + row1)) * D_MODEL + h * DH;
#pragma unroll
    for (int dt = 0; dt < 8; dt++) {
        const int d = dt * 8 + 2 * tig;
        *(uint32_t*)(op0 + d) = pack_h2(o[dt][0] * inv0, o[dt][1] * inv0);
        *(uint32_t*)(op1 + d) = pack_h2(o[dt][2] * inv1, o[dt][3] * inv1);
    }
}

// ============================================================================
// launch
// ============================================================================
extern "C" void kernel_launch(void* const* d_in, const int* in_sizes, int n_in,
                              void* d_out, int out_size)
{
    const float* x  = (const float*)d_in[0];
    const float* Wq = (const float*)d_in[1];
    const float* Wk = (const float*)d_in[2];
    const float* Wv = (const float*)d_in[3];
    const float* Wo = (const float*)d_in[4];
    float* out = (float*)d_out;

    __half *Qp, *Kp, *Vp, *Ap;
    cudaGetSymbolAddress((void**)&Qp, g_Q);
    cudaGetSymbolAddress((void**)&Kp, g_K);
    cudaGetSymbolAddress((void**)&Vp, g_V);
    cudaGetSymbolAddress((void**)&Ap, g_A);

    dim3 ggrid(D_MODEL / 128, M_TOK / 128);   // 8 x 32 = 256 CTAs
    gemm_f16_kernel<2, false><<<ggrid, 256>>>(x, Wq, Qp);   // Q: fp16 + prescale
    gemm_f16_kernel<1, false><<<ggrid, 256>>>(x, Wk, Kp);   // K: fp16
    gemm_f16_kernel<1, false><<<ggrid, 256>>>(x, Wv, Vp);   // V: fp16

    dim3 agrid(S_ / 128, B_ * NH);            // 16 x 32
    attn_f16_kernel<<<agrid, 256>>>(Qp, Kp, Vp, Ap);

    gemm_f16_kernel<0, true><<<ggrid, 256>>>(Ap, Wo, out);  // O proj, fp32 out
}